// round 7
// baseline (speedup 1.0000x reference)
#include <cuda_runtime.h>

// ---------------------------------------------------------------------------
// Problem constants
// ---------------------------------------------------------------------------
#define N_NODES 4096
#define AGGW    1024     // K(16) * WIDTH(64)
#define KSPLIT  8

// ---------------------------------------------------------------------------
// Packed f32x2 helpers (sm_103a FFMA2 path)
// ---------------------------------------------------------------------------
__device__ __forceinline__ unsigned long long ffma2(unsigned long long a,
                                                    unsigned long long b,
                                                    unsigned long long c) {
    unsigned long long d;
    asm("fma.rn.f32x2 %0, %1, %2, %3;" : "=l"(d) : "l"(a), "l"(b), "l"(c));
    return d;
}
__device__ __forceinline__ unsigned long long fpack2(float lo, float hi) {
    unsigned long long r;
    asm("mov.b64 %0, {%1, %2};" : "=l"(r) : "f"(lo), "f"(hi));
    return r;
}
__device__ __forceinline__ float2 funpack2(unsigned long long v) {
    float lo, hi;
    asm("mov.b64 {%0, %1}, %2;" : "=f"(lo), "=f"(hi) : "l"(v));
    return make_float2(lo, hi);
}

// ---------------------------------------------------------------------------
// Scratch (device globals -- no allocation allowed). 16B-aligned for float4.
// ---------------------------------------------------------------------------
__device__ __align__(16) float g_h0[N_NODES * 64];
__device__ __align__(16) float g_agg1[N_NODES * AGGW];
__device__ __align__(16) float g_agg2[N_NODES * AGGW];
__device__ __align__(16) float g_agg3[N_NODES * AGGW];
__device__ __align__(16) float g_cat[N_NODES * 64];
__device__ __align__(16) float g_part[KSPLIT * N_NODES * 64];   // split-K partials
// partial column stats: x: 16 slots * 256 = 4096
//                       h0: 64 slots * 128 = 8192 at offset 4096
//                       cat: 64 slots * 128 = 8192 at offset 12288
__device__ float g_stats[20480];
__device__ int   g_ro[N_NODES + 1];

// ---------------------------------------------------------------------------
// BN fold: reduce nslots partial (sum, sq) -> per-channel scale/bias in smem
// ---------------------------------------------------------------------------
__device__ __forceinline__ void bn_fold(const float* __restrict__ stats, int C,
                                        int nslots,
                                        const float* __restrict__ g,
                                        const float* __restrict__ b,
                                        float* s_sc, float* s_bi,
                                        int t, int nthreads) {
    for (int c = t; c < C; c += nthreads) {
        float s = 0.0f, q = 0.0f;
        for (int bk = 0; bk < nslots; bk++) {
            s += stats[bk * 2 * C + c];
            q += stats[bk * 2 * C + C + c];
        }
        float m = s * (1.0f / N_NODES);
        float v = q * (1.0f / N_NODES) - m * m;
        float rs = rsqrtf(v + 1e-5f);
        float sc = rs * g[c];
        s_sc[c] = sc;
        s_bi[c] = b[c] - m * sc;
    }
}

// ---------------------------------------------------------------------------
// prep: blocks 0..15 -> partial column stats of x (C=128)
//       blocks 16..32 -> CSR row offsets for branch-1 dst (binary search)
// ---------------------------------------------------------------------------
__global__ void prep_k(const float* __restrict__ x, const int* __restrict__ dst,
                       int E, float* __restrict__ stats_x, int* __restrict__ ro) {
    int bx = blockIdx.x;
    if (bx < 16) {
        int c = threadIdx.x;
        if (c < 128) {
            int r0 = bx * 256;
            float s = 0.0f, s2 = 0.0f;
            for (int r = r0; r < r0 + 256; r++) {
                float v = x[(size_t)r * 128 + c];
                s += v;
                s2 += v * v;
            }
            stats_x[bx * 256 + c] = s;
            stats_x[bx * 256 + 128 + c] = s2;
        }
    } else {
        int t = (bx - 16) * 256 + threadIdx.x;
        if (t > N_NODES) return;
        if (t == N_NODES) { ro[t] = E; return; }
        int lo = 0, hi = E;
        while (lo < hi) {
            int mid = (lo + hi) >> 1;
            if (dst[mid] < t) lo = mid + 1; else hi = mid;
        }
        ro[t] = lo;
    }
}

// ---------------------------------------------------------------------------
// gemm_x: merged identity + input GEMMs on A = x [4096,128].
//   blockIdx.x < 4 : out[:, bx*64 : +64] = lrelu(bn_id(x)) @ id_W
//   blockIdx.x == 4: h0 = lrelu(bn_in(x)) @ in_W, + per-block h0 column stats
// ---------------------------------------------------------------------------
__global__ __launch_bounds__(256) void gemm_x_k(
    const float* __restrict__ x, const float* __restrict__ stats_x,
    const float* __restrict__ id_g, const float* __restrict__ id_b,
    const float* __restrict__ idW,
    const float* __restrict__ in_g, const float* __restrict__ in_b,
    const float* __restrict__ inW,
    float* __restrict__ out, float* __restrict__ h0,
    float* __restrict__ stats_h) {
    __shared__ float s_sc[128], s_bi[128];
    __shared__ __align__(16) float As[16][65];
    __shared__ __align__(16) float Bs[16][64];
    __shared__ float hs[64], hq[64];
    int t = threadIdx.x;
    int bx = blockIdx.x;
    bool idp = bx < 4;
    bn_fold(stats_x, 128, 16, idp ? id_g : in_g, idp ? id_b : in_b, s_sc, s_bi, t, 256);

    const float* B = idp ? idW : inW;
    int Nd = idp ? 256 : 64;
    int n0 = idp ? bx * 64 : 0;
    float* C = idp ? out : h0;
    int m0 = blockIdx.y * 64;
    int tx = t & 15, ty = t >> 4;
    int lam = t >> 2, lak = (t & 3) << 2;
    int lbk = t >> 4, lbn = (t & 15) << 2;
    float acc[4][4];
#pragma unroll
    for (int r = 0; r < 4; r++)
#pragma unroll
        for (int cc = 0; cc < 4; cc++) acc[r][cc] = 0.0f;
    if (t < 64) { hs[t] = 0.0f; hq[t] = 0.0f; }
    __syncthreads();

    for (int k0 = 0; k0 < 128; k0 += 16) {
        float4 av = *(const float4*)(x + (size_t)(m0 + lam) * 128 + k0 + lak);
        float v;
        v = av.x * s_sc[k0 + lak + 0] + s_bi[k0 + lak + 0]; av.x = v > 0.0f ? v : 0.1f * v;
        v = av.y * s_sc[k0 + lak + 1] + s_bi[k0 + lak + 1]; av.y = v > 0.0f ? v : 0.1f * v;
        v = av.z * s_sc[k0 + lak + 2] + s_bi[k0 + lak + 2]; av.z = v > 0.0f ? v : 0.1f * v;
        v = av.w * s_sc[k0 + lak + 3] + s_bi[k0 + lak + 3]; av.w = v > 0.0f ? v : 0.1f * v;
        As[lak + 0][lam] = av.x;
        As[lak + 1][lam] = av.y;
        As[lak + 2][lam] = av.z;
        As[lak + 3][lam] = av.w;
        float4 bv = *(const float4*)(B + (size_t)(k0 + lbk) * Nd + n0 + lbn);
        *(float4*)&Bs[lbk][lbn] = bv;
        __syncthreads();
#pragma unroll
        for (int kk = 0; kk < 16; kk++) {
            float a0 = As[kk][ty * 4 + 0];
            float a1 = As[kk][ty * 4 + 1];
            float a2 = As[kk][ty * 4 + 2];
            float a3 = As[kk][ty * 4 + 3];
            float4 b = *(const float4*)&Bs[kk][tx * 4];
            acc[0][0] += a0 * b.x; acc[0][1] += a0 * b.y; acc[0][2] += a0 * b.z; acc[0][3] += a0 * b.w;
            acc[1][0] += a1 * b.x; acc[1][1] += a1 * b.y; acc[1][2] += a1 * b.z; acc[1][3] += a1 * b.w;
            acc[2][0] += a2 * b.x; acc[2][1] += a2 * b.y; acc[2][2] += a2 * b.z; acc[2][3] += a2 * b.w;
            acc[3][0] += a3 * b.x; acc[3][1] += a3 * b.y; acc[3][2] += a3 * b.z; acc[3][3] += a3 * b.w;
        }
        __syncthreads();
    }
#pragma unroll
    for (int r = 0; r < 4; r++) {
        int m = m0 + ty * 4 + r;
#pragma unroll
        for (int cc = 0; cc < 4; cc++)
            C[(size_t)m * Nd + n0 + tx * 4 + cc] = acc[r][cc];
    }
    if (!idp) {
#pragma unroll
        for (int cc = 0; cc < 4; cc++) {
            float s = acc[0][cc] + acc[1][cc] + acc[2][cc] + acc[3][cc];
            float q = acc[0][cc] * acc[0][cc] + acc[1][cc] * acc[1][cc] +
                      acc[2][cc] * acc[2][cc] + acc[3][cc] * acc[3][cc];
            atomicAdd(&hs[tx * 4 + cc], s);
            atomicAdd(&hq[tx * 4 + cc], q);
        }
        __syncthreads();
        if (t < 64) {
            stats_h[blockIdx.y * 128 + t] = hs[t];
            stats_h[blockIdx.y * 128 + 64 + t] = hq[t];
        }
    }
}

// ---------------------------------------------------------------------------
// Fused edge aggregation for ALL THREE branches in one pass over branch-1 CSR.
// (R4-measured version: separate B1 loops, packed f32x2 Phase C.)
// ---------------------------------------------------------------------------
#define EB 32
__global__ __launch_bounds__(256) void edge_all_k(
    const float* __restrict__ h0, const float* __restrict__ pos,
    const float* __restrict__ ori, const int* __restrict__ seq,
    const int* __restrict__ src, const int* __restrict__ ro,
    const float* __restrict__ Ws1, const float* __restrict__ bs1,
    const float* __restrict__ Ws2, const float* __restrict__ bs2,
    const float* __restrict__ Ws3, const float* __restrict__ bs3,
    const float* __restrict__ stats_h,
    const float* __restrict__ mid_g, const float* __restrict__ mid_b,
    float* __restrict__ agg1, float* __restrict__ agg2, float* __restrict__ agg3) {
    const double R2SQ = 1.8 * 1.8;
    const double R3T  = 0.75 * 1.8;
    const double R3SQ = R3T * R3T;
    __shared__ float s_sc[64], s_bi[64];
    __shared__ float s_fri[9];
    __shared__ float s_posi[3];
    __shared__ int   s_seqi;
    __shared__ float s_d[EB];
    __shared__ int   s_in2[EB], s_in3[EB];
    __shared__ float s_feat[EB][6];
    __shared__ int   s_ds[EB], s_src[EB];
    __shared__ __align__(16) unsigned long long s_wp[EB][16][4]; // {w1,w1}{w2,w2}{w3,w3}pad
    __shared__ __align__(16) float s_h[EB][64];

    int i = blockIdx.x;
    int t = threadIdx.x;
    bn_fold(stats_h, 64, 64, mid_g, mid_b, s_sc, s_bi, t, 256);
    if (t < 9)  s_fri[t] = ori[i * 9 + t];
    if (t >= 9 && t < 12) s_posi[t - 9] = pos[i * 3 + (t - 9)];
    if (t == 12) s_seqi = seq[i];

    int start = ro[i], end = ro[i + 1];
    unsigned long long A1lo = 0ull, A1hi = 0ull;
    unsigned long long A2lo = 0ull, A2hi = 0ull;
    unsigned long long A3lo = 0ull, A3hi = 0ull;
    int k = t >> 4, c0 = (t & 15) << 2;
    __syncthreads();

    for (int e0 = start; e0 < end; e0 += EB) {
        int ne = min(EB, end - e0);
        // --- Phase A: per-edge geometry (1 thread per edge) ---
        if (t < ne) {
            int js = src[e0 + t];
            s_src[t] = js;
            float dx = __fadd_rn(pos[js * 3 + 0], -s_posi[0]);
            float dy = __fadd_rn(pos[js * 3 + 1], -s_posi[1]);
            float dz = __fadd_rn(pos[js * 3 + 2], -s_posi[2]);
            float d2 = __fadd_rn(__fadd_rn(__fmul_rn(dx, dx), __fmul_rn(dy, dy)),
                                 __fmul_rn(dz, dz));
            double d2d = (double)d2;
            s_in2[t] = (d2d <= R2SQ) ? 1 : 0;
            s_in3[t] = (d2d <= R3SQ) ? 1 : 0;
            float dist = sqrtf(d2);
            s_d[t] = dist;
            float inv = 1.0f / (dist + 1e-9f);
            float ux = dx * inv, uy = dy * inv, uz = dz * inv;
            float f0 = s_fri[0], f1 = s_fri[1], f2 = s_fri[2];
            float f3 = s_fri[3], f4 = s_fri[4], f5 = s_fri[5];
            float f6 = s_fri[6], f7 = s_fri[7], f8 = s_fri[8];
            s_feat[t][0] = f0 * ux + f1 * uy + f2 * uz;
            s_feat[t][1] = f3 * ux + f4 * uy + f5 * uz;
            s_feat[t][2] = f6 * ux + f7 * uy + f8 * uz;
            const float* op = ori + (size_t)js * 9;
            s_feat[t][3] = f0 * op[0] + f1 * op[1] + f2 * op[2];
            s_feat[t][4] = f3 * op[3] + f4 * op[4] + f5 * op[5];
            s_feat[t][5] = f6 * op[6] + f7 * op[7] + f8 * op[8];
            s_ds[t] = seq[js] - s_seqi;
        }
        __syncthreads();
        // --- Phase B1: edge weights per branch (stored duplicated) ---
        for (int task = t; task < ne * 16; task += 256) {   // branch 1
            int e = task >> 4, kk = task & 15;
            int d = s_ds[e]; d = max(-2, min(2, d));
            int idx = d + 2;
            const float* wr = Ws1 + idx * 112 + kk;
            float s = bs1[idx * 16 + kk] + (s_d[e] / 2.7f) * wr[0];
#pragma unroll
            for (int cc = 0; cc < 6; cc++) s += s_feat[e][cc] * wr[(cc + 1) * 16];
            s = s > 0.0f ? s : 0.2f * s;
            s_wp[e][kk][0] = fpack2(s, s);
        }
        for (int task = t; task < ne * 16; task += 256) {   // branch 2
            int e = task >> 4, kk = task & 15;
            float w = 0.0f;
            if (s_in2[e]) {
                int d = s_ds[e]; d = max(-3, min(3, d));
                int idx = d + 3;
                const float* wr = Ws2 + idx * 112 + kk;
                float s = bs2[idx * 16 + kk] + (s_d[e] / 1.8f) * wr[0];
#pragma unroll
                for (int cc = 0; cc < 6; cc++) s += s_feat[e][cc] * wr[(cc + 1) * 16];
                w = s > 0.0f ? s : 0.2f * s;
            }
            s_wp[e][kk][1] = fpack2(w, w);
        }
        for (int task = t; task < ne * 16; task += 256) {   // branch 3
            int e = task >> 4, kk = task & 15;
            float w = 0.0f;
            if (s_in3[e]) {
                int d = s_ds[e]; d = max(-5, min(5, d));
                int idx = d + 5;
                const float* wr = Ws3 + idx * 112 + kk;
                float s = bs3[idx * 16 + kk] + (s_d[e] / 1.35f) * wr[0];
#pragma unroll
                for (int cc = 0; cc < 6; cc++) s += s_feat[e][cc] * wr[(cc + 1) * 16];
                w = s > 0.0f ? s : 0.2f * s;
            }
            s_wp[e][kk][2] = fpack2(w, w);
        }
        // --- Phase B2: gather h0 rows with mid-BN + lrelu folded in ---
        for (int task = t; task < ne * 16; task += 256) {
            int e = task >> 4, q = task & 15;
            int cc = q << 2;
            float4 v = *(const float4*)(h0 + (size_t)s_src[e] * 64 + cc);
            float u;
            u = v.x * s_sc[cc + 0] + s_bi[cc + 0]; v.x = u > 0.0f ? u : 0.1f * u;
            u = v.y * s_sc[cc + 1] + s_bi[cc + 1]; v.y = u > 0.0f ? u : 0.1f * u;
            u = v.z * s_sc[cc + 2] + s_bi[cc + 2]; v.z = u > 0.0f ? u : 0.1f * u;
            u = v.w * s_sc[cc + 3] + s_bi[cc + 3]; v.w = u > 0.0f ? u : 0.1f * u;
            *(float4*)&s_h[e][cc] = v;
        }
        __syncthreads();
        // --- Phase C: packed rank-1 accumulate: 3 LDS + 6 FFMA2 per edge ---
        for (int e = 0; e < ne; e++) {
            ulonglong2 h2 = *(const ulonglong2*)&s_h[e][c0];
            ulonglong2 w12 = *(const ulonglong2*)&s_wp[e][k][0];
            unsigned long long w3p = s_wp[e][k][2];
            A1lo = ffma2(w12.x, h2.x, A1lo); A1hi = ffma2(w12.x, h2.y, A1hi);
            A2lo = ffma2(w12.y, h2.x, A2lo); A2hi = ffma2(w12.y, h2.y, A2hi);
            A3lo = ffma2(w3p,  h2.x, A3lo); A3hi = ffma2(w3p,  h2.y, A3hi);
        }
        __syncthreads();
    }
    size_t off = (size_t)i * AGGW + k * 64 + c0;
    float2 lo, hi;
    lo = funpack2(A1lo); hi = funpack2(A1hi);
    *(float4*)(agg1 + off) = make_float4(lo.x, lo.y, hi.x, hi.y);
    lo = funpack2(A2lo); hi = funpack2(A2hi);
    *(float4*)(agg2 + off) = make_float4(lo.x, lo.y, hi.x, hi.y);
    lo = funpack2(A3lo); hi = funpack2(A3hi);
    *(float4*)(agg3 + off) = make_float4(lo.x, lo.y, hi.x, hi.y);
}

// ---------------------------------------------------------------------------
// agg GEMMs, split-K, register-tiled, DOUBLE-BUFFERED:
//   grid (3, 32, KSPLIT), 128 threads, BM=128, BK=16.
//   Global->reg prefetch of tile j+1 overlaps compute of tile j; 1 sync/iter.
// ---------------------------------------------------------------------------
__global__ __launch_bounds__(128) void gemm_agg_k(
    const float* __restrict__ agg1, const float* __restrict__ agg2,
    const float* __restrict__ agg3,
    const float* __restrict__ W1, const float* __restrict__ W2,
    const float* __restrict__ W3, float* __restrict__ part) {
    __shared__ __align__(16) float As_t[2][16][132];
    __shared__ __align__(16) float Bs[2][16][32];
    int bx = blockIdx.x;
    int m0 = blockIdx.y * 128;
    int kz = blockIdx.z;
    const float* A; const float* B; int ldb, coff, BN;
    if (bx == 0)      { A = agg1; B = W1; ldb = 32; coff = 0;  BN = 32; }
    else if (bx == 1) { A = agg2; B = W2; ldb = 16; coff = 32; BN = 16; }
    else              { A = agg3; B = W3; ldb = 16; coff = 48; BN = 16; }
    int t = threadIdx.x;
    int ty = t >> 3, tx = t & 7;     // ty: 16 row-groups of 8; tx: 8 col-groups
    float acc[8][4];
#pragma unroll
    for (int r = 0; r < 8; r++)
#pragma unroll
        for (int c = 0; c < 4; c++) acc[r][c] = 0.0f;
    int kbase = kz * (1024 / KSPLIT);
    const int NIT = (1024 / KSPLIT) / 16;   // 8

    // A-load geometry (fixed per thread)
    int arow = t >> 2;               // 0..31 within each 32-row group
    int akq = (t & 3) << 2;          // k-quad
    int nf = BN >> 2;
    bool bload = t < 16 * nf;
    int brow = bload ? (t / nf) : 0;
    int bcq = bload ? ((t % nf) << 2) : 0;

    float4 av[4]; float4 bv;
    // prologue: fetch + store tile 0
    {
        int k0 = kbase;
#pragma unroll
        for (int j = 0; j < 4; j++)
            av[j] = *(const float4*)(A + (size_t)(m0 + j * 32 + arow) * 1024 + k0 + akq);
        if (bload)
            bv = *(const float4*)(B + (size_t)(k0 + brow) * ldb + bcq);
#pragma unroll
        for (int j = 0; j < 4; j++) {
            int row = j * 32 + arow;
            As_t[0][akq + 0][row] = av[j].x;
            As_t[0][akq + 1][row] = av[j].y;
            As_t[0][akq + 2][row] = av[j].z;
            As_t[0][akq + 3][row] = av[j].w;
        }
        if (bload) *(float4*)&Bs[0][brow][bcq] = bv;
    }
    __syncthreads();
    int cur = 0;

    for (int iter = 0; iter < NIT; iter++) {
        bool has_next = (iter + 1) < NIT;
        if (has_next) {
            int k0 = kbase + (iter + 1) * 16;
#pragma unroll
            for (int j = 0; j < 4; j++)
                av[j] = *(const float4*)(A + (size_t)(m0 + j * 32 + arow) * 1024 + k0 + akq);
            if (bload)
                bv = *(const float4*)(B + (size_t)(k0 + brow) * ldb + bcq);
        }
        // compute from smem[cur]
        if (BN == 32) {
#pragma unroll
            for (int kk = 0; kk < 16; kk++) {
                float4 alo = *(const float4*)&As_t[cur][kk][ty * 8];
                float4 ahi = *(const float4*)&As_t[cur][kk][ty * 8 + 4];
                float4 b = *(const float4*)&Bs[cur][kk][tx * 4];
                float a[8] = {alo.x, alo.y, alo.z, alo.w,
                              ahi.x, ahi.y, ahi.z, ahi.w};
#pragma unroll
                for (int r = 0; r < 8; r++) {
                    acc[r][0] += a[r] * b.x;
                    acc[r][1] += a[r] * b.y;
                    acc[r][2] += a[r] * b.z;
                    acc[r][3] += a[r] * b.w;
                }
            }
        } else {
#pragma unroll
            for (int kk = 0; kk < 16; kk++) {
                float4 alo = *(const float4*)&As_t[cur][kk][ty * 8];
                float4 ahi = *(const float4*)&As_t[cur][kk][ty * 8 + 4];
                float2 b = *(const float2*)&Bs[cur][kk][tx * 2];
                float a[8] = {alo.x, alo.y, alo.z, alo.w,
                              ahi.x, ahi.y, ahi.z, ahi.w};
#pragma unroll
                for (int r = 0; r < 8; r++) {
                    acc[r][0] += a[r] * b.x;
                    acc[r][1] += a[r] * b.y;
                }
            }
        }
        if (has_next) {
            int nxt = cur ^ 1;
#pragma unroll
            for (int j = 0; j < 4; j++) {
                int row = j * 32 + arow;
                As_t[nxt][akq + 0][row] = av[j].x;
                As_t[nxt][akq + 1][row] = av[j].y;
                As_t[nxt][akq + 2][row] = av[j].z;
                As_t[nxt][akq + 3][row] = av[j].w;
            }
            if (bload) *(float4*)&Bs[nxt][brow][bcq] = bv;
            __syncthreads();
            cur = nxt;
        }
    }
    float* P = part + (size_t)kz * (N_NODES * 64);
    if (BN == 32) {
#pragma unroll
        for (int r = 0; r < 8; r++) {
            size_t m = (size_t)(m0 + ty * 8 + r);
            *(float4*)&P[m * 64 + coff + tx * 4] =
                make_float4(acc[r][0], acc[r][1], acc[r][2], acc[r][3]);
        }
    } else {
#pragma unroll
        for (int r = 0; r < 8; r++) {
            size_t m = (size_t)(m0 + ty * 8 + r);
            *(float2*)&P[m * 64 + coff + tx * 2] = make_float2(acc[r][0], acc[r][1]);
        }
    }
}

// ---------------------------------------------------------------------------
// reduce_k: cat = sum of KSPLIT split-K partials; emit per-block cat stats.
// grid 64 blocks x 256 threads; block handles 64 rows.
// ---------------------------------------------------------------------------
__global__ __launch_bounds__(256) void reduce_k(
    const float* __restrict__ part, float* __restrict__ cat,
    float* __restrict__ stats_c) {
    __shared__ float cs[64], cq[64];
    int by = blockIdx.x;
    int t = threadIdx.x;
    if (t < 64) { cs[t] = 0.0f; cq[t] = 0.0f; }
    __syncthreads();
    int r0 = (t >> 4) * 4;
    int c = (t & 15) * 4;
    float s[4] = {0, 0, 0, 0}, q[4] = {0, 0, 0, 0};
#pragma unroll
    for (int j = 0; j < 4; j++) {
        size_t off = ((size_t)(by * 64 + r0 + j)) * 64 + c;
        float4 v = make_float4(0.f, 0.f, 0.f, 0.f);
#pragma unroll
        for (int p = 0; p < KSPLIT; p++) {
            float4 u = *(const float4*)(part + (size_t)p * (N_NODES * 64) + off);
            v.x += u.x; v.y += u.y; v.z += u.z; v.w += u.w;
        }
        *(float4*)(cat + off) = v;
        s[0] += v.x; q[0] += v.x * v.x;
        s[1] += v.y; q[1] += v.y * v.y;
        s[2] += v.z; q[2] += v.z * v.z;
        s[3] += v.w; q[3] += v.w * v.w;
    }
#pragma unroll
    for (int j = 0; j < 4; j++) {
        atomicAdd(&cs[c + j], s[j]);
        atomicAdd(&cq[c + j], q[j]);
    }
    __syncthreads();
    if (t < 64) {
        stats_c[by * 128 + t] = cs[t];
        stats_c[by * 128 + 64 + t] = cq[t];
    }
}

// ---------------------------------------------------------------------------
// Output GEMM: out += lrelu(bn_out(cat)) @ out_W   [4096,64]x[64,256]
// ---------------------------------------------------------------------------
__global__ __launch_bounds__(256) void gemm_out_k(
    const float* __restrict__ cat, const float* __restrict__ stats_c,
    const float* __restrict__ out_g, const float* __restrict__ out_b,
    const float* __restrict__ outW, float* __restrict__ out) {
    __shared__ float s_sc[64], s_bi[64];
    __shared__ __align__(16) float As[16][65];
    __shared__ __align__(16) float Bs[16][64];
    int t = threadIdx.x;
    bn_fold(stats_c, 64, 64, out_g, out_b, s_sc, s_bi, t, 256);
    int n0 = blockIdx.x * 64;
    int m0 = blockIdx.y * 64;
    int tx = t & 15, ty = t >> 4;
    int lam = t >> 2, lak = (t & 3) << 2;
    int lbk = t >> 4, lbn = (t & 15) << 2;
    float acc[4][4];
#pragma unroll
    for (int r = 0; r < 4; r++)
#pragma unroll
        for (int cc = 0; cc < 4; cc++) acc[r][cc] = 0.0f;
    __syncthreads();

    for (int k0 = 0; k0 < 64; k0 += 16) {
        float4 av = *(const float4*)(cat + (size_t)(m0 + lam) * 64 + k0 + lak);
        float v;
        v = av.x * s_sc[k0 + lak + 0] + s_bi[k0 + lak + 0]; av.x = v > 0.0f ? v : 0.1f * v;
        v = av.y * s_sc[k0 + lak + 1] + s_bi[k0 + lak + 1]; av.y = v > 0.0f ? v : 0.1f * v;
        v = av.z * s_sc[k0 + lak + 2] + s_bi[k0 + lak + 2]; av.z = v > 0.0f ? v : 0.1f * v;
        v = av.w * s_sc[k0 + lak + 3] + s_bi[k0 + lak + 3]; av.w = v > 0.0f ? v : 0.1f * v;
        As[lak + 0][lam] = av.x;
        As[lak + 1][lam] = av.y;
        As[lak + 2][lam] = av.z;
        As[lak + 3][lam] = av.w;
        float4 bv = *(const float4*)(outW + (size_t)(k0 + lbk) * 256 + n0 + lbn);
        *(float4*)&Bs[lbk][lbn] = bv;
        __syncthreads();
#pragma unroll
        for (int kk = 0; kk < 16; kk++) {
            float a0 = As[kk][ty * 4 + 0];
            float a1 = As[kk][ty * 4 + 1];
            float a2 = As[kk][ty * 4 + 2];
            float a3 = As[kk][ty * 4 + 3];
            float4 b = *(const float4*)&Bs[kk][tx * 4];
            acc[0][0] += a0 * b.x; acc[0][1] += a0 * b.y; acc[0][2] += a0 * b.z; acc[0][3] += a0 * b.w;
            acc[1][0] += a1 * b.x; acc[1][1] += a1 * b.y; acc[1][2] += a1 * b.z; acc[1][3] += a1 * b.w;
            acc[2][0] += a2 * b.x; acc[2][1] += a2 * b.y; acc[2][2] += a2 * b.z; acc[2][3] += a2 * b.w;
            acc[3][0] += a3 * b.x; acc[3][1] += a3 * b.y; acc[3][2] += a3 * b.z; acc[3][3] += a3 * b.w;
        }
        __syncthreads();
    }
#pragma unroll
    for (int r = 0; r < 4; r++) {
        size_t m = m0 + ty * 4 + r;
#pragma unroll
        for (int cc = 0; cc < 4; cc++) {
            float* p = out + m * 256 + n0 + tx * 4 + cc;
            *p += acc[r][cc];
        }
    }
}

// ---------------------------------------------------------------------------
// Launch
// ---------------------------------------------------------------------------
extern "C" void kernel_launch(void* const* d_in, const int* in_sizes, int n_in,
                              void* d_out, int out_size) {
    const float* x    = (const float*)d_in[0];
    const float* pos  = (const float*)d_in[1];
    const float* ori  = (const float*)d_in[2];
    const int*   seq  = (const int*)d_in[3];
    // d_in[4] = batch (implied by graph)
    const int* src1 = (const int*)d_in[5];
    const int* dst1 = (const int*)d_in[6];
    // src2/dst2, src3/dst3 unused: nested-radius property recovers them
    const float* id_g = (const float*)d_in[11];
    const float* id_b = (const float*)d_in[12];
    const float* id_W = (const float*)d_in[13];
    const float* in_g = (const float*)d_in[14];
    const float* in_b = (const float*)d_in[15];
    const float* in_W = (const float*)d_in[16];
    const float* mid_g = (const float*)d_in[17];
    const float* mid_b = (const float*)d_in[18];
    const float* Ws1 = (const float*)d_in[19];
    const float* bs1 = (const float*)d_in[20];
    const float* W1  = (const float*)d_in[21];
    const float* Ws2 = (const float*)d_in[22];
    const float* bs2 = (const float*)d_in[23];
    const float* W2  = (const float*)d_in[24];
    const float* Ws3 = (const float*)d_in[25];
    const float* bs3 = (const float*)d_in[26];
    const float* W3  = (const float*)d_in[27];
    const float* out_g = (const float*)d_in[28];
    const float* out_b = (const float*)d_in[29];
    const float* out_W = (const float*)d_in[30];
    float* out = (float*)d_out;

    int E1 = in_sizes[5];

    float *h0, *agg1, *agg2, *agg3, *cat, *part, *stats;
    int* ro;
    cudaGetSymbolAddress((void**)&h0, g_h0);
    cudaGetSymbolAddress((void**)&agg1, g_agg1);
    cudaGetSymbolAddress((void**)&agg2, g_agg2);
    cudaGetSymbolAddress((void**)&agg3, g_agg3);
    cudaGetSymbolAddress((void**)&cat, g_cat);
    cudaGetSymbolAddress((void**)&part, g_part);
    cudaGetSymbolAddress((void**)&stats, g_stats);
    cudaGetSymbolAddress((void**)&ro, g_ro);
    float* stats_x = stats;              // 16 slots * 256
    float* stats_h = stats + 4096;       // 64 slots * 128
    float* stats_c = stats + 12288;      // 64 slots * 128

    // 1. x column stats + branch-1 CSR
    prep_k<<<33, 256>>>(x, dst1, E1, stats_x, ro);
    // 2. identity GEMM -> out, input GEMM -> h0 (+ h0 stats)
    gemm_x_k<<<dim3(5, 64), 256>>>(x, stats_x, id_g, id_b, id_W,
                                   in_g, in_b, in_W, out, h0, stats_h);
    // 3. fused 3-branch edge aggregation (mid-BN folded in)
    edge_all_k<<<N_NODES, 256>>>(h0, pos, ori, seq, src1, ro,
                                 Ws1, bs1, Ws2, bs2, Ws3, bs3,
                                 stats_h, mid_g, mid_b, agg1, agg2, agg3);
    // 4. agg GEMMs, split-K, register-tiled, double-buffered (768 blocks)
    gemm_agg_k<<<dim3(3, 32, KSPLIT), 128>>>(agg1, agg2, agg3, W1, W2, W3, part);
    // 5. reduce partials -> cat (+ cat stats)
    reduce_k<<<64, 256>>>(part, cat, stats_c);
    // 6. output GEMM, accumulate onto identity
    gemm_out_k<<<dim3(4, 64), 256>>>(cat, stats_c, out_g, out_b, out_W, out);
}

// round 9
// speedup vs baseline: 1.0905x; 1.0905x over previous
#include <cuda_runtime.h>
#include <cuda_fp16.h>

// ---------------------------------------------------------------------------
// Problem constants
// ---------------------------------------------------------------------------
#define N_NODES 4096
#define AGGW    1024     // K(16) * WIDTH(64)
#define KSPLIT  8

// ---------------------------------------------------------------------------
// Packed f32x2 helpers (sm_103a FFMA2 path)
// ---------------------------------------------------------------------------
__device__ __forceinline__ unsigned long long ffma2(unsigned long long a,
                                                    unsigned long long b,
                                                    unsigned long long c) {
    unsigned long long d;
    asm("fma.rn.f32x2 %0, %1, %2, %3;" : "=l"(d) : "l"(a), "l"(b), "l"(c));
    return d;
}
__device__ __forceinline__ unsigned long long fpack2(float lo, float hi) {
    unsigned long long r;
    asm("mov.b64 %0, {%1, %2};" : "=l"(r) : "f"(lo), "f"(hi));
    return r;
}
__device__ __forceinline__ float2 funpack2(unsigned long long v) {
    float lo, hi;
    asm("mov.b64 {%0, %1}, %2;" : "=f"(lo), "=f"(hi) : "l"(v));
    return make_float2(lo, hi);
}

// ---------------------------------------------------------------------------
// Scratch (device globals -- no allocation allowed). 16B-aligned for float4.
// agg intermediates are fp16: halves DRAM traffic of the dominant stream
// (fp16 chosen over bf16: measured bf16 rel_err 1.43e-3 exceeded threshold;
//  fp16's 8x finer mantissa puts it at ~2e-4).
// ---------------------------------------------------------------------------
__device__ __align__(16) float g_h0[N_NODES * 64];
__device__ __align__(16) __half g_agg1[N_NODES * AGGW];
__device__ __align__(16) __half g_agg2[N_NODES * AGGW];
__device__ __align__(16) __half g_agg3[N_NODES * AGGW];
__device__ __align__(16) float g_cat[N_NODES * 64];
__device__ __align__(16) float g_part[KSPLIT * N_NODES * 64];   // split-K partials
// partial column stats: x: 16 slots * 256 = 4096
//                       h0: 64 slots * 128 = 8192 at offset 4096
//                       cat: 64 slots * 128 = 8192 at offset 12288
__device__ float g_stats[20480];
__device__ int   g_ro[N_NODES + 1];

// ---------------------------------------------------------------------------
// BN fold: reduce nslots partial (sum, sq) -> per-channel scale/bias in smem
// ---------------------------------------------------------------------------
__device__ __forceinline__ void bn_fold(const float* __restrict__ stats, int C,
                                        int nslots,
                                        const float* __restrict__ g,
                                        const float* __restrict__ b,
                                        float* s_sc, float* s_bi,
                                        int t, int nthreads) {
    for (int c = t; c < C; c += nthreads) {
        float s = 0.0f, q = 0.0f;
        for (int bk = 0; bk < nslots; bk++) {
            s += stats[bk * 2 * C + c];
            q += stats[bk * 2 * C + C + c];
        }
        float m = s * (1.0f / N_NODES);
        float v = q * (1.0f / N_NODES) - m * m;
        float rs = rsqrtf(v + 1e-5f);
        float sc = rs * g[c];
        s_sc[c] = sc;
        s_bi[c] = b[c] - m * sc;
    }
}

// ---------------------------------------------------------------------------
// prep: blocks 0..15 -> partial column stats of x (C=128)
//       blocks 16..32 -> CSR row offsets for branch-1 dst (binary search)
// ---------------------------------------------------------------------------
__global__ void prep_k(const float* __restrict__ x, const int* __restrict__ dst,
                       int E, float* __restrict__ stats_x, int* __restrict__ ro) {
    int bx = blockIdx.x;
    if (bx < 16) {
        int c = threadIdx.x;
        if (c < 128) {
            int r0 = bx * 256;
            float s = 0.0f, s2 = 0.0f;
            for (int r = r0; r < r0 + 256; r++) {
                float v = x[(size_t)r * 128 + c];
                s += v;
                s2 += v * v;
            }
            stats_x[bx * 256 + c] = s;
            stats_x[bx * 256 + 128 + c] = s2;
        }
    } else {
        int t = (bx - 16) * 256 + threadIdx.x;
        if (t > N_NODES) return;
        if (t == N_NODES) { ro[t] = E; return; }
        int lo = 0, hi = E;
        while (lo < hi) {
            int mid = (lo + hi) >> 1;
            if (dst[mid] < t) lo = mid + 1; else hi = mid;
        }
        ro[t] = lo;
    }
}

// ---------------------------------------------------------------------------
// gemm_x: merged identity + input GEMMs on A = x [4096,128].
//   blockIdx.x < 4 : out[:, bx*64 : +64] = lrelu(bn_id(x)) @ id_W
//   blockIdx.x == 4: h0 = lrelu(bn_in(x)) @ in_W, + per-block h0 column stats
// ---------------------------------------------------------------------------
__global__ __launch_bounds__(256) void gemm_x_k(
    const float* __restrict__ x, const float* __restrict__ stats_x,
    const float* __restrict__ id_g, const float* __restrict__ id_b,
    const float* __restrict__ idW,
    const float* __restrict__ in_g, const float* __restrict__ in_b,
    const float* __restrict__ inW,
    float* __restrict__ out, float* __restrict__ h0,
    float* __restrict__ stats_h) {
    __shared__ float s_sc[128], s_bi[128];
    __shared__ __align__(16) float As[16][65];
    __shared__ __align__(16) float Bs[16][64];
    __shared__ float hs[64], hq[64];
    int t = threadIdx.x;
    int bx = blockIdx.x;
    bool idp = bx < 4;
    bn_fold(stats_x, 128, 16, idp ? id_g : in_g, idp ? id_b : in_b, s_sc, s_bi, t, 256);

    const float* B = idp ? idW : inW;
    int Nd = idp ? 256 : 64;
    int n0 = idp ? bx * 64 : 0;
    float* C = idp ? out : h0;
    int m0 = blockIdx.y * 64;
    int tx = t & 15, ty = t >> 4;
    int lam = t >> 2, lak = (t & 3) << 2;
    int lbk = t >> 4, lbn = (t & 15) << 2;
    float acc[4][4];
#pragma unroll
    for (int r = 0; r < 4; r++)
#pragma unroll
        for (int cc = 0; cc < 4; cc++) acc[r][cc] = 0.0f;
    if (t < 64) { hs[t] = 0.0f; hq[t] = 0.0f; }
    __syncthreads();

    for (int k0 = 0; k0 < 128; k0 += 16) {
        float4 av = *(const float4*)(x + (size_t)(m0 + lam) * 128 + k0 + lak);
        float v;
        v = av.x * s_sc[k0 + lak + 0] + s_bi[k0 + lak + 0]; av.x = v > 0.0f ? v : 0.1f * v;
        v = av.y * s_sc[k0 + lak + 1] + s_bi[k0 + lak + 1]; av.y = v > 0.0f ? v : 0.1f * v;
        v = av.z * s_sc[k0 + lak + 2] + s_bi[k0 + lak + 2]; av.z = v > 0.0f ? v : 0.1f * v;
        v = av.w * s_sc[k0 + lak + 3] + s_bi[k0 + lak + 3]; av.w = v > 0.0f ? v : 0.1f * v;
        As[lak + 0][lam] = av.x;
        As[lak + 1][lam] = av.y;
        As[lak + 2][lam] = av.z;
        As[lak + 3][lam] = av.w;
        float4 bv = *(const float4*)(B + (size_t)(k0 + lbk) * Nd + n0 + lbn);
        *(float4*)&Bs[lbk][lbn] = bv;
        __syncthreads();
#pragma unroll
        for (int kk = 0; kk < 16; kk++) {
            float a0 = As[kk][ty * 4 + 0];
            float a1 = As[kk][ty * 4 + 1];
            float a2 = As[kk][ty * 4 + 2];
            float a3 = As[kk][ty * 4 + 3];
            float4 b = *(const float4*)&Bs[kk][tx * 4];
            acc[0][0] += a0 * b.x; acc[0][1] += a0 * b.y; acc[0][2] += a0 * b.z; acc[0][3] += a0 * b.w;
            acc[1][0] += a1 * b.x; acc[1][1] += a1 * b.y; acc[1][2] += a1 * b.z; acc[1][3] += a1 * b.w;
            acc[2][0] += a2 * b.x; acc[2][1] += a2 * b.y; acc[2][2] += a2 * b.z; acc[2][3] += a2 * b.w;
            acc[3][0] += a3 * b.x; acc[3][1] += a3 * b.y; acc[3][2] += a3 * b.z; acc[3][3] += a3 * b.w;
        }
        __syncthreads();
    }
#pragma unroll
    for (int r = 0; r < 4; r++) {
        int m = m0 + ty * 4 + r;
#pragma unroll
        for (int cc = 0; cc < 4; cc++)
            C[(size_t)m * Nd + n0 + tx * 4 + cc] = acc[r][cc];
    }
    if (!idp) {
#pragma unroll
        for (int cc = 0; cc < 4; cc++) {
            float s = acc[0][cc] + acc[1][cc] + acc[2][cc] + acc[3][cc];
            float q = acc[0][cc] * acc[0][cc] + acc[1][cc] * acc[1][cc] +
                      acc[2][cc] * acc[2][cc] + acc[3][cc] * acc[3][cc];
            atomicAdd(&hs[tx * 4 + cc], s);
            atomicAdd(&hq[tx * 4 + cc], q);
        }
        __syncthreads();
        if (t < 64) {
            stats_h[blockIdx.y * 128 + t] = hs[t];
            stats_h[blockIdx.y * 128 + 64 + t] = hq[t];
        }
    }
}

// ---------------------------------------------------------------------------
// Fused edge aggregation for ALL THREE branches in one pass over branch-1 CSR.
// (R4/R6-measured structure; agg stores in fp16.)
// ---------------------------------------------------------------------------
#define EB 32
__global__ __launch_bounds__(256) void edge_all_k(
    const float* __restrict__ h0, const float* __restrict__ pos,
    const float* __restrict__ ori, const int* __restrict__ seq,
    const int* __restrict__ src, const int* __restrict__ ro,
    const float* __restrict__ Ws1, const float* __restrict__ bs1,
    const float* __restrict__ Ws2, const float* __restrict__ bs2,
    const float* __restrict__ Ws3, const float* __restrict__ bs3,
    const float* __restrict__ stats_h,
    const float* __restrict__ mid_g, const float* __restrict__ mid_b,
    __half* __restrict__ agg1, __half* __restrict__ agg2,
    __half* __restrict__ agg3) {
    const double R2SQ = 1.8 * 1.8;
    const double R3T  = 0.75 * 1.8;
    const double R3SQ = R3T * R3T;
    __shared__ float s_sc[64], s_bi[64];
    __shared__ float s_fri[9];
    __shared__ float s_posi[3];
    __shared__ int   s_seqi;
    __shared__ float s_d[EB];
    __shared__ int   s_in2[EB], s_in3[EB];
    __shared__ float s_feat[EB][6];
    __shared__ int   s_ds[EB], s_src[EB];
    __shared__ __align__(16) unsigned long long s_wp[EB][16][4]; // {w1,w1}{w2,w2}{w3,w3}pad
    __shared__ __align__(16) float s_h[EB][64];

    int i = blockIdx.x;
    int t = threadIdx.x;
    bn_fold(stats_h, 64, 64, mid_g, mid_b, s_sc, s_bi, t, 256);
    if (t < 9)  s_fri[t] = ori[i * 9 + t];
    if (t >= 9 && t < 12) s_posi[t - 9] = pos[i * 3 + (t - 9)];
    if (t == 12) s_seqi = seq[i];

    int start = ro[i], end = ro[i + 1];
    unsigned long long A1lo = 0ull, A1hi = 0ull;
    unsigned long long A2lo = 0ull, A2hi = 0ull;
    unsigned long long A3lo = 0ull, A3hi = 0ull;
    int k = t >> 4, c0 = (t & 15) << 2;
    __syncthreads();

    for (int e0 = start; e0 < end; e0 += EB) {
        int ne = min(EB, end - e0);
        // --- Phase A: per-edge geometry (1 thread per edge) ---
        if (t < ne) {
            int js = src[e0 + t];
            s_src[t] = js;
            float dx = __fadd_rn(pos[js * 3 + 0], -s_posi[0]);
            float dy = __fadd_rn(pos[js * 3 + 1], -s_posi[1]);
            float dz = __fadd_rn(pos[js * 3 + 2], -s_posi[2]);
            float d2 = __fadd_rn(__fadd_rn(__fmul_rn(dx, dx), __fmul_rn(dy, dy)),
                                 __fmul_rn(dz, dz));
            double d2d = (double)d2;
            s_in2[t] = (d2d <= R2SQ) ? 1 : 0;
            s_in3[t] = (d2d <= R3SQ) ? 1 : 0;
            float dist = sqrtf(d2);
            s_d[t] = dist;
            float inv = 1.0f / (dist + 1e-9f);
            float ux = dx * inv, uy = dy * inv, uz = dz * inv;
            float f0 = s_fri[0], f1 = s_fri[1], f2 = s_fri[2];
            float f3 = s_fri[3], f4 = s_fri[4], f5 = s_fri[5];
            float f6 = s_fri[6], f7 = s_fri[7], f8 = s_fri[8];
            s_feat[t][0] = f0 * ux + f1 * uy + f2 * uz;
            s_feat[t][1] = f3 * ux + f4 * uy + f5 * uz;
            s_feat[t][2] = f6 * ux + f7 * uy + f8 * uz;
            const float* op = ori + (size_t)js * 9;
            s_feat[t][3] = f0 * op[0] + f1 * op[1] + f2 * op[2];
            s_feat[t][4] = f3 * op[3] + f4 * op[4] + f5 * op[5];
            s_feat[t][5] = f6 * op[6] + f7 * op[7] + f8 * op[8];
            s_ds[t] = seq[js] - s_seqi;
        }
        __syncthreads();
        // --- Phase B1: edge weights per branch (stored duplicated) ---
        for (int task = t; task < ne * 16; task += 256) {   // branch 1
            int e = task >> 4, kk = task & 15;
            int d = s_ds[e]; d = max(-2, min(2, d));
            int idx = d + 2;
            const float* wr = Ws1 + idx * 112 + kk;
            float s = bs1[idx * 16 + kk] + (s_d[e] / 2.7f) * wr[0];
#pragma unroll
            for (int cc = 0; cc < 6; cc++) s += s_feat[e][cc] * wr[(cc + 1) * 16];
            s = s > 0.0f ? s : 0.2f * s;
            s_wp[e][kk][0] = fpack2(s, s);
        }
        for (int task = t; task < ne * 16; task += 256) {   // branch 2
            int e = task >> 4, kk = task & 15;
            float w = 0.0f;
            if (s_in2[e]) {
                int d = s_ds[e]; d = max(-3, min(3, d));
                int idx = d + 3;
                const float* wr = Ws2 + idx * 112 + kk;
                float s = bs2[idx * 16 + kk] + (s_d[e] / 1.8f) * wr[0];
#pragma unroll
                for (int cc = 0; cc < 6; cc++) s += s_feat[e][cc] * wr[(cc + 1) * 16];
                w = s > 0.0f ? s : 0.2f * s;
            }
            s_wp[e][kk][1] = fpack2(w, w);
        }
        for (int task = t; task < ne * 16; task += 256) {   // branch 3
            int e = task >> 4, kk = task & 15;
            float w = 0.0f;
            if (s_in3[e]) {
                int d = s_ds[e]; d = max(-5, min(5, d));
                int idx = d + 5;
                const float* wr = Ws3 + idx * 112 + kk;
                float s = bs3[idx * 16 + kk] + (s_d[e] / 1.35f) * wr[0];
#pragma unroll
                for (int cc = 0; cc < 6; cc++) s += s_feat[e][cc] * wr[(cc + 1) * 16];
                w = s > 0.0f ? s : 0.2f * s;
            }
            s_wp[e][kk][2] = fpack2(w, w);
        }
        // --- Phase B2: gather h0 rows with mid-BN + lrelu folded in ---
        for (int task = t; task < ne * 16; task += 256) {
            int e = task >> 4, q = task & 15;
            int cc = q << 2;
            float4 v = *(const float4*)(h0 + (size_t)s_src[e] * 64 + cc);
            float u;
            u = v.x * s_sc[cc + 0] + s_bi[cc + 0]; v.x = u > 0.0f ? u : 0.1f * u;
            u = v.y * s_sc[cc + 1] + s_bi[cc + 1]; v.y = u > 0.0f ? u : 0.1f * u;
            u = v.z * s_sc[cc + 2] + s_bi[cc + 2]; v.z = u > 0.0f ? u : 0.1f * u;
            u = v.w * s_sc[cc + 3] + s_bi[cc + 3]; v.w = u > 0.0f ? u : 0.1f * u;
            *(float4*)&s_h[e][cc] = v;
        }
        __syncthreads();
        // --- Phase C: packed rank-1 accumulate: 3 LDS + 6 FFMA2 per edge ---
        for (int e = 0; e < ne; e++) {
            ulonglong2 h2 = *(const ulonglong2*)&s_h[e][c0];
            ulonglong2 w12 = *(const ulonglong2*)&s_wp[e][k][0];
            unsigned long long w3p = s_wp[e][k][2];
            A1lo = ffma2(w12.x, h2.x, A1lo); A1hi = ffma2(w12.x, h2.y, A1hi);
            A2lo = ffma2(w12.y, h2.x, A2lo); A2hi = ffma2(w12.y, h2.y, A2hi);
            A3lo = ffma2(w3p,  h2.x, A3lo); A3hi = ffma2(w3p,  h2.y, A3hi);
        }
        __syncthreads();
    }
    size_t off = (size_t)i * AGGW + k * 64 + c0;
    {
        float2 lo = funpack2(A1lo), hi = funpack2(A1hi);
        union { __half2 h2[2]; uint2 u; } cv;
        cv.h2[0] = __float22half2_rn(lo);
        cv.h2[1] = __float22half2_rn(hi);
        *(uint2*)(agg1 + off) = cv.u;
    }
    {
        float2 lo = funpack2(A2lo), hi = funpack2(A2hi);
        union { __half2 h2[2]; uint2 u; } cv;
        cv.h2[0] = __float22half2_rn(lo);
        cv.h2[1] = __float22half2_rn(hi);
        *(uint2*)(agg2 + off) = cv.u;
    }
    {
        float2 lo = funpack2(A3lo), hi = funpack2(A3hi);
        union { __half2 h2[2]; uint2 u; } cv;
        cv.h2[0] = __float22half2_rn(lo);
        cv.h2[1] = __float22half2_rn(hi);
        *(uint2*)(agg3 + off) = cv.u;
    }
}

// ---------------------------------------------------------------------------
// agg GEMMs, split-K, register-tiled, double-buffered, fp16 A:
//   grid (3, 32, KSPLIT), 128 threads, BM=128, BK=16.
// ---------------------------------------------------------------------------
__global__ __launch_bounds__(128) void gemm_agg_k(
    const __half* __restrict__ agg1, const __half* __restrict__ agg2,
    const __half* __restrict__ agg3,
    const float* __restrict__ W1, const float* __restrict__ W2,
    const float* __restrict__ W3, float* __restrict__ part) {
    __shared__ __align__(16) float As_t[2][16][132];
    __shared__ __align__(16) float Bs[2][16][32];
    int bx = blockIdx.x;
    int m0 = blockIdx.y * 128;
    int kz = blockIdx.z;
    const __half* A; const float* B; int ldb, coff, BN;
    if (bx == 0)      { A = agg1; B = W1; ldb = 32; coff = 0;  BN = 32; }
    else if (bx == 1) { A = agg2; B = W2; ldb = 16; coff = 32; BN = 16; }
    else              { A = agg3; B = W3; ldb = 16; coff = 48; BN = 16; }
    int t = threadIdx.x;
    int ty = t >> 3, tx = t & 7;     // ty: 16 row-groups of 8; tx: 8 col-groups
    float acc[8][4];
#pragma unroll
    for (int r = 0; r < 8; r++)
#pragma unroll
        for (int c = 0; c < 4; c++) acc[r][c] = 0.0f;
    int kbase = kz * (1024 / KSPLIT);
    const int NIT = (1024 / KSPLIT) / 16;   // 8

    // A-load geometry (fixed per thread): 4 fp16 per load (uint2, 8B)
    int arow = t >> 2;               // 0..31 within each 32-row group
    int akq = (t & 3) << 2;          // k-quad
    int nf = BN >> 2;
    bool bload = t < 16 * nf;
    int brow = bload ? (t / nf) : 0;
    int bcq = bload ? ((t % nf) << 2) : 0;

    float4 av[4]; float4 bv;
    // prologue: fetch + store tile 0
    {
        int k0 = kbase;
#pragma unroll
        for (int j = 0; j < 4; j++) {
            uint2 raw = *(const uint2*)(A + (size_t)(m0 + j * 32 + arow) * 1024 + k0 + akq);
            float2 lo = __half22float2(*(__half2*)&raw.x);
            float2 hi = __half22float2(*(__half2*)&raw.y);
            av[j] = make_float4(lo.x, lo.y, hi.x, hi.y);
        }
        if (bload)
            bv = *(const float4*)(B + (size_t)(k0 + brow) * ldb + bcq);
#pragma unroll
        for (int j = 0; j < 4; j++) {
            int row = j * 32 + arow;
            As_t[0][akq + 0][row] = av[j].x;
            As_t[0][akq + 1][row] = av[j].y;
            As_t[0][akq + 2][row] = av[j].z;
            As_t[0][akq + 3][row] = av[j].w;
        }
        if (bload) *(float4*)&Bs[0][brow][bcq] = bv;
    }
    __syncthreads();
    int cur = 0;

    for (int iter = 0; iter < NIT; iter++) {
        bool has_next = (iter + 1) < NIT;
        if (has_next) {
            int k0 = kbase + (iter + 1) * 16;
#pragma unroll
            for (int j = 0; j < 4; j++) {
                uint2 raw = *(const uint2*)(A + (size_t)(m0 + j * 32 + arow) * 1024 + k0 + akq);
                float2 lo = __half22float2(*(__half2*)&raw.x);
                float2 hi = __half22float2(*(__half2*)&raw.y);
                av[j] = make_float4(lo.x, lo.y, hi.x, hi.y);
            }
            if (bload)
                bv = *(const float4*)(B + (size_t)(k0 + brow) * ldb + bcq);
        }
        // compute from smem[cur]
        if (BN == 32) {
#pragma unroll
            for (int kk = 0; kk < 16; kk++) {
                float4 alo = *(const float4*)&As_t[cur][kk][ty * 8];
                float4 ahi = *(const float4*)&As_t[cur][kk][ty * 8 + 4];
                float4 b = *(const float4*)&Bs[cur][kk][tx * 4];
                float a[8] = {alo.x, alo.y, alo.z, alo.w,
                              ahi.x, ahi.y, ahi.z, ahi.w};
#pragma unroll
                for (int r = 0; r < 8; r++) {
                    acc[r][0] += a[r] * b.x;
                    acc[r][1] += a[r] * b.y;
                    acc[r][2] += a[r] * b.z;
                    acc[r][3] += a[r] * b.w;
                }
            }
        } else {
#pragma unroll
            for (int kk = 0; kk < 16; kk++) {
                float4 alo = *(const float4*)&As_t[cur][kk][ty * 8];
                float4 ahi = *(const float4*)&As_t[cur][kk][ty * 8 + 4];
                float2 b = *(const float2*)&Bs[cur][kk][tx * 2];
                float a[8] = {alo.x, alo.y, alo.z, alo.w,
                              ahi.x, ahi.y, ahi.z, ahi.w};
#pragma unroll
                for (int r = 0; r < 8; r++) {
                    acc[r][0] += a[r] * b.x;
                    acc[r][1] += a[r] * b.y;
                }
            }
        }
        if (has_next) {
            int nxt = cur ^ 1;
#pragma unroll
            for (int j = 0; j < 4; j++) {
                int row = j * 32 + arow;
                As_t[nxt][akq + 0][row] = av[j].x;
                As_t[nxt][akq + 1][row] = av[j].y;
                As_t[nxt][akq + 2][row] = av[j].z;
                As_t[nxt][akq + 3][row] = av[j].w;
            }
            if (bload) *(float4*)&Bs[nxt][brow][bcq] = bv;
            __syncthreads();
            cur = nxt;
        }
    }
    float* P = part + (size_t)kz * (N_NODES * 64);
    if (BN == 32) {
#pragma unroll
        for (int r = 0; r < 8; r++) {
            size_t m = (size_t)(m0 + ty * 8 + r);
            *(float4*)&P[m * 64 + coff + tx * 4] =
                make_float4(acc[r][0], acc[r][1], acc[r][2], acc[r][3]);
        }
    } else {
#pragma unroll
        for (int r = 0; r < 8; r++) {
            size_t m = (size_t)(m0 + ty * 8 + r);
            *(float2*)&P[m * 64 + coff + tx * 2] = make_float2(acc[r][0], acc[r][1]);
        }
    }
}

// ---------------------------------------------------------------------------
// reduce_k: cat = sum of KSPLIT split-K partials; emit per-block cat stats.
// grid 64 blocks x 256 threads; block handles 64 rows.
// ---------------------------------------------------------------------------
__global__ __launch_bounds__(256) void reduce_k(
    const float* __restrict__ part, float* __restrict__ cat,
    float* __restrict__ stats_c) {
    __shared__ float cs[64], cq[64];
    int by = blockIdx.x;
    int t = threadIdx.x;
    if (t < 64) { cs[t] = 0.0f; cq[t] = 0.0f; }
    __syncthreads();
    int r0 = (t >> 4) * 4;
    int c = (t & 15) * 4;
    float s[4] = {0, 0, 0, 0}, q[4] = {0, 0, 0, 0};
#pragma unroll
    for (int j = 0; j < 4; j++) {
        size_t off = ((size_t)(by * 64 + r0 + j)) * 64 + c;
        float4 v = make_float4(0.f, 0.f, 0.f, 0.f);
#pragma unroll
        for (int p = 0; p < KSPLIT; p++) {
            float4 u = *(const float4*)(part + (size_t)p * (N_NODES * 64) + off);
            v.x += u.x; v.y += u.y; v.z += u.z; v.w += u.w;
        }
        *(float4*)(cat + off) = v;
        s[0] += v.x; q[0] += v.x * v.x;
        s[1] += v.y; q[1] += v.y * v.y;
        s[2] += v.z; q[2] += v.z * v.z;
        s[3] += v.w; q[3] += v.w * v.w;
    }
#pragma unroll
    for (int j = 0; j < 4; j++) {
        atomicAdd(&cs[c + j], s[j]);
        atomicAdd(&cq[c + j], q[j]);
    }
    __syncthreads();
    if (t < 64) {
        stats_c[by * 128 + t] = cs[t];
        stats_c[by * 128 + 64 + t] = cq[t];
    }
}

// ---------------------------------------------------------------------------
// Output GEMM: out += lrelu(bn_out(cat)) @ out_W   [4096,64]x[64,256]
// ---------------------------------------------------------------------------
__global__ __launch_bounds__(256) void gemm_out_k(
    const float* __restrict__ cat, const float* __restrict__ stats_c,
    const float* __restrict__ out_g, const float* __restrict__ out_b,
    const float* __restrict__ outW, float* __restrict__ out) {
    __shared__ float s_sc[64], s_bi[64];
    __shared__ __align__(16) float As[16][65];
    __shared__ __align__(16) float Bs[16][64];
    int t = threadIdx.x;
    bn_fold(stats_c, 64, 64, out_g, out_b, s_sc, s_bi, t, 256);
    int n0 = blockIdx.x * 64;
    int m0 = blockIdx.y * 64;
    int tx = t & 15, ty = t >> 4;
    int lam = t >> 2, lak = (t & 3) << 2;
    int lbk = t >> 4, lbn = (t & 15) << 2;
    float acc[4][4];
#pragma unroll
    for (int r = 0; r < 4; r++)
#pragma unroll
        for (int cc = 0; cc < 4; cc++) acc[r][cc] = 0.0f;
    __syncthreads();

    for (int k0 = 0; k0 < 64; k0 += 16) {
        float4 av = *(const float4*)(cat + (size_t)(m0 + lam) * 64 + k0 + lak);
        float v;
        v = av.x * s_sc[k0 + lak + 0] + s_bi[k0 + lak + 0]; av.x = v > 0.0f ? v : 0.1f * v;
        v = av.y * s_sc[k0 + lak + 1] + s_bi[k0 + lak + 1]; av.y = v > 0.0f ? v : 0.1f * v;
        v = av.z * s_sc[k0 + lak + 2] + s_bi[k0 + lak + 2]; av.z = v > 0.0f ? v : 0.1f * v;
        v = av.w * s_sc[k0 + lak + 3] + s_bi[k0 + lak + 3]; av.w = v > 0.0f ? v : 0.1f * v;
        As[lak + 0][lam] = av.x;
        As[lak + 1][lam] = av.y;
        As[lak + 2][lam] = av.z;
        As[lak + 3][lam] = av.w;
        float4 bv = *(const float4*)(outW + (size_t)(k0 + lbk) * 256 + n0 + lbn);
        *(float4*)&Bs[lbk][lbn] = bv;
        __syncthreads();
#pragma unroll
        for (int kk = 0; kk < 16; kk++) {
            float a0 = As[kk][ty * 4 + 0];
            float a1 = As[kk][ty * 4 + 1];
            float a2 = As[kk][ty * 4 + 2];
            float a3 = As[kk][ty * 4 + 3];
            float4 b = *(const float4*)&Bs[kk][tx * 4];
            acc[0][0] += a0 * b.x; acc[0][1] += a0 * b.y; acc[0][2] += a0 * b.z; acc[0][3] += a0 * b.w;
            acc[1][0] += a1 * b.x; acc[1][1] += a1 * b.y; acc[1][2] += a1 * b.z; acc[1][3] += a1 * b.w;
            acc[2][0] += a2 * b.x; acc[2][1] += a2 * b.y; acc[2][2] += a2 * b.z; acc[2][3] += a2 * b.w;
            acc[3][0] += a3 * b.x; acc[3][1] += a3 * b.y; acc[3][2] += a3 * b.z; acc[3][3] += a3 * b.w;
        }
        __syncthreads();
    }
#pragma unroll
    for (int r = 0; r < 4; r++) {
        size_t m = m0 + ty * 4 + r;
#pragma unroll
        for (int cc = 0; cc < 4; cc++) {
            float* p = out + m * 256 + n0 + tx * 4 + cc;
            *p += acc[r][cc];
        }
    }
}

// ---------------------------------------------------------------------------
// Launch
// ---------------------------------------------------------------------------
extern "C" void kernel_launch(void* const* d_in, const int* in_sizes, int n_in,
                              void* d_out, int out_size) {
    const float* x    = (const float*)d_in[0];
    const float* pos  = (const float*)d_in[1];
    const float* ori  = (const float*)d_in[2];
    const int*   seq  = (const int*)d_in[3];
    // d_in[4] = batch (implied by graph)
    const int* src1 = (const int*)d_in[5];
    const int* dst1 = (const int*)d_in[6];
    // src2/dst2, src3/dst3 unused: nested-radius property recovers them
    const float* id_g = (const float*)d_in[11];
    const float* id_b = (const float*)d_in[12];
    const float* id_W = (const float*)d_in[13];
    const float* in_g = (const float*)d_in[14];
    const float* in_b = (const float*)d_in[15];
    const float* in_W = (const float*)d_in[16];
    const float* mid_g = (const float*)d_in[17];
    const float* mid_b = (const float*)d_in[18];
    const float* Ws1 = (const float*)d_in[19];
    const float* bs1 = (const float*)d_in[20];
    const float* W1  = (const float*)d_in[21];
    const float* Ws2 = (const float*)d_in[22];
    const float* bs2 = (const float*)d_in[23];
    const float* W2  = (const float*)d_in[24];
    const float* Ws3 = (const float*)d_in[25];
    const float* bs3 = (const float*)d_in[26];
    const float* W3  = (const float*)d_in[27];
    const float* out_g = (const float*)d_in[28];
    const float* out_b = (const float*)d_in[29];
    const float* out_W = (const float*)d_in[30];
    float* out = (float*)d_out;

    int E1 = in_sizes[5];

    float *h0, *cat, *part, *stats;
    __half *agg1, *agg2, *agg3;
    int* ro;
    cudaGetSymbolAddress((void**)&h0, g_h0);
    cudaGetSymbolAddress((void**)&agg1, g_agg1);
    cudaGetSymbolAddress((void**)&agg2, g_agg2);
    cudaGetSymbolAddress((void**)&agg3, g_agg3);
    cudaGetSymbolAddress((void**)&cat, g_cat);
    cudaGetSymbolAddress((void**)&part, g_part);
    cudaGetSymbolAddress((void**)&stats, g_stats);
    cudaGetSymbolAddress((void**)&ro, g_ro);
    float* stats_x = stats;              // 16 slots * 256
    float* stats_h = stats + 4096;       // 64 slots * 128
    float* stats_c = stats + 12288;      // 64 slots * 128

    // 1. x column stats + branch-1 CSR
    prep_k<<<33, 256>>>(x, dst1, E1, stats_x, ro);
    // 2. identity GEMM -> out, input GEMM -> h0 (+ h0 stats)
    gemm_x_k<<<dim3(5, 64), 256>>>(x, stats_x, id_g, id_b, id_W,
                                   in_g, in_b, in_W, out, h0, stats_h);
    // 3. fused 3-branch edge aggregation (mid-BN folded in), fp16 agg out
    edge_all_k<<<N_NODES, 256>>>(h0, pos, ori, seq, src1, ro,
                                 Ws1, bs1, Ws2, bs2, Ws3, bs3,
                                 stats_h, mid_g, mid_b, agg1, agg2, agg3);
    // 4. agg GEMMs, split-K, register-tiled, double-buffered, fp16 A
    gemm_agg_k<<<dim3(3, 32, KSPLIT), 128>>>(agg1, agg2, agg3, W1, W2, W3, part);
    // 5. reduce partials -> cat (+ cat stats)
    reduce_k<<<64, 256>>>(part, cat, stats_c);
    // 6. output GEMM, accumulate onto identity
    gemm_out_k<<<dim3(4, 64), 256>>>(cat, stats_c, out_g, out_b, out_W, out);
}